// round 15
// baseline (speedup 1.0000x reference)
#include <cuda_runtime.h>
#include <cuda_fp16.h>
#include <cstdint>
#include <cstddef>

// ---------------- problem dims ----------------
#define BB 4096
#define DD 1024
#define HH 4096
#define OO 1024
#define NE 8
#define NAE 5
#define SPLITK 4

// ---------------- device scratch ----------------
__device__ __half g_x16[(size_t)BB * DD];
__device__ __half g_w1h[(size_t)NE * HH * DD];
__device__ __half g_w2h[(size_t)NE * OO * HH];
__device__ __half g_h16[(size_t)NE * BB * HH];
__device__ __half g_part[(size_t)SPLITK * NE * BB * OO];
__device__ float g_gw[(size_t)BB * NE];
__device__ int g_list[(size_t)NE * BB];
__device__ int g_cnt[NE];

// ---------------- helpers ----------------
__device__ __forceinline__ uint32_t smem_u32(const void* p) {
    uint32_t a;
    asm("{ .reg .u64 t; cvta.to.shared.u64 t, %1; cvt.u32.u64 %0, t; }" : "=r"(a) : "l"(p));
    return a;
}
#define SWZ(off) ((off) ^ (((off) >> 3) & 0x70))

__device__ __forceinline__ void cp_async16(uint32_t saddr, const void* gptr) {
    asm volatile("cp.async.cg.shared.global [%0], [%1], 16;\n" :: "r"(saddr), "l"(gptr));
}
__device__ __forceinline__ void cp_commit() {
    asm volatile("cp.async.commit_group;\n" ::: "memory");
}
template <int N>
__device__ __forceinline__ void cp_wait() {
    asm volatile("cp.async.wait_group %0;\n" :: "n"(N) : "memory");
}
__device__ __forceinline__ void ldsm_x4(uint32_t& r0, uint32_t& r1, uint32_t& r2,
                                        uint32_t& r3, uint32_t addr) {
    asm volatile("ldmatrix.sync.aligned.m8n8.x4.shared.b16 {%0,%1,%2,%3}, [%4];"
                 : "=r"(r0), "=r"(r1), "=r"(r2), "=r"(r3) : "r"(addr));
}
__device__ __forceinline__ void mma16816(float* c, const uint32_t* a, const uint32_t* b) {
    asm volatile(
        "mma.sync.aligned.m16n8k16.row.col.f32.f16.f16.f32 "
        "{%0,%1,%2,%3}, {%4,%5,%6,%7}, {%8,%9}, {%0,%1,%2,%3};"
        : "+f"(c[0]), "+f"(c[1]), "+f"(c[2]), "+f"(c[3])
        : "r"(a[0]), "r"(a[1]), "r"(a[2]), "r"(a[3]), "r"(b[0]), "r"(b[1]));
}

// ---------------- gate kernel: Wg cached in smem, 16 tokens/block; also emits x16 ----
#define GTOK 16
__global__ void gate_kernel(const float* __restrict__ x, const float* __restrict__ Wg,
                            const float* __restrict__ bg, float* __restrict__ gw,
                            __half* __restrict__ x16) {
    __shared__ float wgs[NE * DD];
    __shared__ float slog[NE];
    int tid = threadIdx.x, wid = tid >> 5, lid = tid & 31;
    for (int i = tid; i < NE * DD / 4; i += 256)
        reinterpret_cast<float4*>(wgs)[i] = reinterpret_cast<const float4*>(Wg)[i];
    // fused x -> fp16 conversion for this block's 16 tokens (x rows are L2-hot here)
    {
        size_t base4 = (size_t)blockIdx.x * GTOK * DD / 4;
        for (int i = tid; i < GTOK * DD / 4; i += 256) {
            float4 v = reinterpret_cast<const float4*>(x)[base4 + i];
            __half h[4] = {__float2half_rn(v.x), __float2half_rn(v.y),
                           __float2half_rn(v.z), __float2half_rn(v.w)};
            *reinterpret_cast<uint2*>(x16 + (base4 + i) * 4) = *reinterpret_cast<uint2*>(h);
        }
    }
    __syncthreads();
    for (int t = 0; t < GTOK; t++) {
        int b = blockIdx.x * GTOK + t;
        const float* xr = x + (size_t)b * DD;
        const float* wr = wgs + wid * DD;
        float s = 0.f;
        for (int i = lid; i < DD; i += 32) s += xr[i] * wr[i];
#pragma unroll
        for (int o = 16; o > 0; o >>= 1) s += __shfl_xor_sync(0xffffffffu, s, o);
        if (lid == 0) slog[wid] = s + bg[wid];
        __syncthreads();
        if (tid == 0) {
            const float invT = 0.36787944117144233f;
            float l[NE], mx = -1e30f;
#pragma unroll
            for (int i = 0; i < NE; i++) { l[i] = slog[i] * invT; mx = fmaxf(mx, l[i]); }
            float p[NE], se = 0.f;
#pragma unroll
            for (int i = 0; i < NE; i++) { p[i] = expf(l[i] - mx); se += p[i]; }
            float inv_se = 1.f / se;
#pragma unroll
            for (int i = 0; i < NE; i++) p[i] *= inv_se;
            bool sel[NE];
#pragma unroll
            for (int i = 0; i < NE; i++) sel[i] = false;
            float ss = 0.f;
            for (int it = 0; it < NAE; it++) {
                int bi = 0; float bv = -1.f;
#pragma unroll
                for (int i = 0; i < NE; i++)
                    if (!sel[i] && p[i] > bv) { bv = p[i]; bi = i; }
                sel[bi] = true; ss += bv;
            }
            float inv = 1.f / (ss + 1e-8f);
#pragma unroll
            for (int i = 0; i < NE; i++)
                gw[(size_t)b * NE + i] = sel[i] ? p[i] * inv : 0.f;
        }
        __syncthreads();
    }
}

// ---------------- per-expert token list (deterministic, token order) ----------------
__global__ void build_lists(const float* __restrict__ gw, int* __restrict__ list,
                            int* __restrict__ cnt) {
    int z = blockIdx.x, tid = threadIdx.x;
    __shared__ int sbase;
    __shared__ int wtot[8];
    if (tid == 0) sbase = 0;
    __syncthreads();
    for (int t0 = 0; t0 < BB; t0 += 256) {
        int b = t0 + tid;
        int act = gw[(size_t)b * NE + z] > 0.f;
        unsigned m = __ballot_sync(0xffffffffu, act);
        int wid = tid >> 5, lid = tid & 31;
        int wpre = __popc(m & ((1u << lid) - 1u));
        if (lid == 31) wtot[wid] = __popc(m);
        __syncthreads();
        int woff = 0;
        for (int w = 0; w < wid; w++) woff += wtot[w];
        if (act) list[(size_t)z * BB + sbase + woff + wpre] = b;
        __syncthreads();
        if (tid == 0) {
            int tot = 0;
            for (int w = 0; w < 8; w++) tot += wtot[w];
            sbase += tot;
        }
        __syncthreads();
    }
    int c = sbase;
    if (tid == 0) cnt[z] = c;
    int cpad = (c + 127) & ~127;
    for (int i = c + tid; i < cpad; i += 256) list[(size_t)z * BB + i] = 0;
}

// ---------------- merged fp32 -> fp16 conversion (W1, W2) ----------------
__global__ void tohalf2_kernel(const float* __restrict__ b, __half* __restrict__ ob, size_t nb4,
                               const float* __restrict__ c, __half* __restrict__ oc, size_t nc4) {
    size_t total = nb4 + nc4;
    size_t i = (size_t)blockIdx.x * blockDim.x + threadIdx.x;
    size_t str = (size_t)gridDim.x * blockDim.x;
    for (; i < total; i += str) {
        const float* src; __half* dst; size_t j;
        if (i < nb4) { src = b; dst = ob; j = i; }
        else { src = c; dst = oc; j = i - nb4; }
        float4 v = reinterpret_cast<const float4*>(src)[j];
        __half h[4] = {__float2half_rn(v.x), __float2half_rn(v.y),
                       __float2half_rn(v.z), __float2half_rn(v.w)};
        *reinterpret_cast<uint2*>(dst + j * 4) = *reinterpret_cast<uint2*>(h);
    }
}

// ---------------- GEMM config: 128x128 tile, BK=64, 2-stage, 2 CTAs/SM ------------
#define TPB 256
#define ST_SZ 32768            // A 16K + B 16K
#define B_OFF 16384
#define ILIST_OFF (2 * ST_SZ)  // 65536
#define SMEM_SZ (2 * ST_SZ + 512)

// compute one BK=64 chunk: acc += A x B (warp tile 64x32)
__device__ __forceinline__ void compute_chunk(uint32_t sbase, int s, int warp_m,
                                              int warp_n, int lid, float acc[4][4][4]) {
    uint32_t aB = sbase + s * ST_SZ;
    uint32_t bB = aB + B_OFF;
    int rA = warp_m * 64 + (lid & 15);
    int rB = warp_n * 32 + (lid & 15);
    int kh = (lid >> 4) * 16;
#pragma unroll
    for (int ks = 0; ks < 4; ks++) {
        int colb = ks * 32 + kh;
        uint32_t a[4][4];
#pragma unroll
        for (int mf = 0; mf < 4; mf++)
            ldsm_x4(a[mf][0], a[mf][1], a[mf][2], a[mf][3],
                    aB + SWZ((uint32_t)((rA + mf * 16) * 128 + colb)));
        uint32_t b[4][2];
#pragma unroll
        for (int pr = 0; pr < 2; pr++) {
            uint32_t r0, r1, r2, r3;
            ldsm_x4(r0, r1, r2, r3, bB + SWZ((uint32_t)((rB + pr * 16) * 128 + colb)));
            b[pr * 2 + 0][0] = r0; b[pr * 2 + 1][0] = r1;
            b[pr * 2 + 0][1] = r2; b[pr * 2 + 1][1] = r3;
        }
#pragma unroll
        for (int mf = 0; mf < 4; mf++)
#pragma unroll
            for (int nf = 0; nf < 4; nf++)
                mma16816(acc[mf][nf], a[mf], b[nf]);
    }
}

// B loader: 128 rows x 64 cols fp16 from row-major [ldB]
__device__ __forceinline__ void load_B(uint32_t sbase, int s, int tid,
                                       const __half* __restrict__ wrow, int ldB, int kk) {
    uint32_t sb = sbase + s * ST_SZ + B_OFF;
#pragma unroll
    for (int i = 0; i < 4; i++) {
        int u = tid + i * TPB;
        int r = u >> 3, seg = u & 7;
        uint32_t off = SWZ((uint32_t)(r * 128 + seg * 16));
        cp_async16(sb + off, wrow + (size_t)r * ldB + kk + seg * 8);
    }
}

// ===================== layer-1 GEMM (gathered A) =====================
__global__ __launch_bounds__(TPB, 2) void gemm1_kernel(
    const __half* __restrict__ x16,           // [BB][DD]
    const __half* __restrict__ w1h,           // [NE][HH][DD]
    const float* __restrict__ b1,             // [NE][HH]
    const float* __restrict__ gw,             // [BB][NE]
    const int* __restrict__ list, const int* __restrict__ cnt,
    __half* __restrict__ h16) {               // [NE][BB][HH] (compacted rows)
    int z = blockIdx.z;
    int m0 = blockIdx.y * 128;
    int cz = cnt[z];
    if (m0 >= cz) return;
    int n0 = blockIdx.x * 128;

    extern __shared__ __align__(1024) char smem[];
    uint32_t sbase = smem_u32(smem);
    int* silist = reinterpret_cast<int*>(smem + ILIST_OFF);
    int tid = threadIdx.x, lid = tid & 31, wid = tid >> 5;
    int warp_m = wid >> 2, warp_n = wid & 3;

    if (tid < 128) silist[tid] = list[(size_t)z * BB + m0 + tid];
    __syncthreads();

    const __half* wrow = w1h + (size_t)z * HH * DD + (size_t)n0 * DD;
    const int NC = DD / 64;    // 16

    float acc[4][4][4];
#pragma unroll
    for (int a = 0; a < 4; a++)
#pragma unroll
        for (int b = 0; b < 4; b++)
#pragma unroll
            for (int c = 0; c < 4; c++) acc[a][b][c] = 0.f;

    auto issue = [&](int ci) {
        int s = ci & 1, kk = ci * 64;
        uint32_t sa = sbase + s * ST_SZ;
#pragma unroll
        for (int i = 0; i < 4; i++) {
            int u = tid + i * TPB;
            int r = u >> 3, seg = u & 7;
            int tok = silist[r];
            uint32_t off = SWZ((uint32_t)(r * 128 + seg * 16));
            cp_async16(sa + off, x16 + (size_t)tok * DD + kk + seg * 8);
        }
        load_B(sbase, s, tid, wrow, DD, kk);
        cp_commit();
    };

    issue(0);
    for (int ci = 0; ci < NC; ci++) {
        if (ci + 1 < NC) { issue(ci + 1); cp_wait<1>(); } else { cp_wait<0>(); }
        __syncthreads();
        compute_chunk(sbase, ci & 1, warp_m, warp_n, lid, acc);
        __syncthreads();
    }

    // epilogue: bias + relu, gw-scale, round to fp16 -> h16[z][m0+row][col]
    int g = lid >> 2, t4 = lid & 3;
    const float* bias = b1 + (size_t)z * HH;
    __half* hz = h16 + (size_t)z * BB * HH;
#pragma unroll
    for (int mf = 0; mf < 4; mf++) {
#pragma unroll
        for (int h = 0; h < 2; h++) {
            int row_l = warp_m * 64 + mf * 16 + g + h * 8;
            int tok = silist[row_l];
            float wv = gw[(size_t)tok * NE + z];
            size_t rbase = (size_t)(m0 + row_l) * HH;
#pragma unroll
            for (int nf = 0; nf < 4; nf++) {
                int col = n0 + warp_n * 32 + nf * 8 + t4 * 2;
                float2 bz = *reinterpret_cast<const float2*>(bias + col);
                float v0 = fmaxf(acc[mf][nf][h * 2 + 0] + bz.x, 0.f) * wv;
                float v1 = fmaxf(acc[mf][nf][h * 2 + 1] + bz.y, 0.f) * wv;
                __half h0 = __float2half_rn(v0);
                __half h1 = __float2half_rn(v1);
                uint32_t hp = ((uint32_t)__half_as_ushort(h1) << 16) |
                              (uint32_t)__half_as_ushort(h0);
                *reinterpret_cast<uint32_t*>(hz + rbase + col) = hp;
            }
        }
    }
}

// ===================== layer-2 GEMM (compacted A, split-K=4, fp16 partials) ========
__global__ __launch_bounds__(TPB, 2) void gemm2_kernel(
    const __half* __restrict__ h16,           // [NE][BB][HH]
    const __half* __restrict__ w2h,           // [NE][OO][HH]
    const int* __restrict__ list, const int* __restrict__ cnt,
    __half* __restrict__ part) {              // [SPLITK][NE][BB][OO] fp16
    int zz = blockIdx.z;
    int z = zz & 7;
    int kq = zz >> 3;                         // 0..3 quarter-K piece
    int m0 = blockIdx.y * 128;
    int cz = cnt[z];
    if (m0 >= cz) return;
    int n0 = blockIdx.x * 128;

    extern __shared__ __align__(1024) char smem[];
    uint32_t sbase = smem_u32(smem);
    int tid = threadIdx.x, lid = tid & 31, wid = tid >> 5;
    int warp_m = wid >> 2, warp_n = wid & 3;

    const __half* abase = h16 + (size_t)z * BB * HH + (size_t)m0 * HH + kq * (HH / SPLITK);
    const __half* wrow = w2h + (size_t)z * OO * HH + (size_t)n0 * HH + kq * (HH / SPLITK);
    const int NC = HH / (64 * SPLITK);   // 16 chunks of 64 over quarter of H

    float acc[4][4][4];
#pragma unroll
    for (int a = 0; a < 4; a++)
#pragma unroll
        for (int b = 0; b < 4; b++)
#pragma unroll
            for (int c = 0; c < 4; c++) acc[a][b][c] = 0.f;

    auto issue = [&](int ci) {
        int s = ci & 1, kk = ci * 64;
        uint32_t sa = sbase + s * ST_SZ;
#pragma unroll
        for (int i = 0; i < 4; i++) {
            int u = tid + i * TPB;
            int r = u >> 3, seg = u & 7;
            uint32_t off = SWZ((uint32_t)(r * 128 + seg * 16));
            cp_async16(sa + off, abase + (size_t)r * HH + kk + seg * 8);
        }
        load_B(sbase, s, tid, wrow, HH, kk);
        cp_commit();
    };

    issue(0);
    for (int ci = 0; ci < NC; ci++) {
        if (ci + 1 < NC) { issue(ci + 1); cp_wait<1>(); } else { cp_wait<0>(); }
        __syncthreads();
        compute_chunk(sbase, ci & 1, warp_m, warp_n, lid, acc);
        __syncthreads();
    }

    // epilogue: scatter fp16 partial rows to part[kq][z][token], mask padded rows
    int g = lid >> 2, t4 = lid & 3;
    __half* pz = part + ((size_t)kq * NE + z) * BB * OO;
    const int* lrow = list + (size_t)z * BB + m0;
#pragma unroll
    for (int mf = 0; mf < 4; mf++) {
#pragma unroll
        for (int h = 0; h < 2; h++) {
            int row_l = warp_m * 64 + mf * 16 + g + h * 8;
            if (m0 + row_l < cz) {
                int tok = lrow[row_l];
                size_t rbase = (size_t)tok * OO;
#pragma unroll
                for (int nf = 0; nf < 4; nf++) {
                    int col = n0 + warp_n * 32 + nf * 8 + t4 * 2;
                    __half p0 = __float2half_rn(acc[mf][nf][h * 2 + 0]);
                    __half p1 = __float2half_rn(acc[mf][nf][h * 2 + 1]);
                    uint32_t pp = ((uint32_t)__half_as_ushort(p1) << 16) |
                                  (uint32_t)__half_as_ushort(p0);
                    *reinterpret_cast<uint32_t*>(pz + rbase + col) = pp;
                }
            }
        }
    }
}

// ===================== reduce: out = sum quarters/experts + sum_z gw*b2 ==============
__global__ void reduce_kernel(const __half* __restrict__ part, const float* __restrict__ b2,
                              const float* __restrict__ gw, float* __restrict__ out) {
    const size_t n4 = (size_t)BB * OO / 4;
    size_t i = (size_t)blockIdx.x * blockDim.x + threadIdx.x;
    if (i >= n4) return;
    size_t b = i / (OO / 4);
    int o4 = (int)(i - b * (OO / 4));
    float4 acc = make_float4(0.f, 0.f, 0.f, 0.f);
#pragma unroll
    for (int z = 0; z < NE; z++) {
        float wv = gw[b * NE + z];
        float4 bz = reinterpret_cast<const float4*>(b2)[(size_t)z * (OO / 4) + o4];
        acc.x += wv * bz.x; acc.y += wv * bz.y;
        acc.z += wv * bz.z; acc.w += wv * bz.w;
        if (wv > 0.f) {
            size_t ebase = (size_t)z * BB * OO + b * OO + (size_t)o4 * 4;
#pragma unroll
            for (int q = 0; q < SPLITK; q++) {
                const __half2* p = reinterpret_cast<const __half2*>(
                    part + (size_t)q * NE * BB * OO + ebase);
                float2 a0 = __half22float2(p[0]);
                float2 a1 = __half22float2(p[1]);
                acc.x += a0.x; acc.y += a0.y;
                acc.z += a1.x; acc.w += a1.y;
            }
        }
    }
    reinterpret_cast<float4*>(out)[i] = acc;
}

// ---------------- host launcher ----------------
extern "C" void kernel_launch(void* const* d_in, const int* in_sizes, int n_in,
                              void* d_out, int out_size) {
    const float* x  = (const float*)d_in[0];
    const float* W1 = (const float*)d_in[1];
    const float* b1 = (const float*)d_in[2];
    const float* W2 = (const float*)d_in[3];
    const float* b2 = (const float*)d_in[4];
    const float* Wg = (const float*)d_in[5];
    const float* bg = (const float*)d_in[6];
    float* out = (float*)d_out;

    void *px16, *pw1h, *pw2h, *ph16, *pgw, *ppart, *plist, *pcnt;
    cudaGetSymbolAddress(&px16, g_x16);
    cudaGetSymbolAddress(&pw1h, g_w1h);
    cudaGetSymbolAddress(&pw2h, g_w2h);
    cudaGetSymbolAddress(&ph16, g_h16);
    cudaGetSymbolAddress(&pgw, g_gw);
    cudaGetSymbolAddress(&ppart, g_part);
    cudaGetSymbolAddress(&plist, g_list);
    cudaGetSymbolAddress(&pcnt, g_cnt);

    cudaFuncSetAttribute(gemm1_kernel, cudaFuncAttributeMaxDynamicSharedMemorySize, SMEM_SZ);
    cudaFuncSetAttribute(gemm2_kernel, cudaFuncAttributeMaxDynamicSharedMemorySize, SMEM_SZ);

    gate_kernel<<<BB / GTOK, 256>>>(x, Wg, bg, (float*)pgw, (__half*)px16);
    build_lists<<<NE, 256>>>((const float*)pgw, (int*)plist, (int*)pcnt);
    tohalf2_kernel<<<16384, 256>>>(
        W1, (__half*)pw1h, (size_t)NE * HH * DD / 4,
        W2, (__half*)pw2h, (size_t)NE * OO * HH / 4);

    // layer 1: compacted tokens per expert
    gemm1_kernel<<<dim3(HH / 128, BB / 128, NE), TPB, SMEM_SZ>>>(
        (const __half*)px16, (const __half*)pw1h, b1, (const float*)pgw,
        (const int*)plist, (const int*)pcnt, (__half*)ph16);

    // layer 2: compacted rows, split-K=4, fp16 partials
    gemm2_kernel<<<dim3(OO / 128, BB / 128, SPLITK * NE), TPB, SMEM_SZ>>>(
        (const __half*)ph16, (const __half*)pw2h,
        (const int*)plist, (const int*)pcnt, (__half*)ppart);

    reduce_kernel<<<(BB * OO / 4 + 255) / 256, 256>>>(
        (const __half*)ppart, b2, (const float*)pgw, out);
}

// round 16
// speedup vs baseline: 1.0214x; 1.0214x over previous
#include <cuda_runtime.h>
#include <cuda_fp16.h>
#include <cstdint>
#include <cstddef>

// ---------------- problem dims ----------------
#define BB 4096
#define DD 1024
#define HH 4096
#define OO 1024
#define NE 8
#define NAE 5

// ---------------- device scratch ----------------
__device__ __half g_x16[(size_t)BB * DD];
__device__ __half g_w1h[(size_t)NE * HH * DD];
__device__ __half g_w2h[(size_t)NE * OO * HH];
__device__ __half g_h16[(size_t)NE * BB * HH];
__device__ __half g_part[(size_t)2 * NE * BB * OO];
__device__ float g_gw[(size_t)BB * NE];
__device__ int g_list[(size_t)NE * BB];
__device__ int g_cnt[NE];

// ---------------- helpers ----------------
__device__ __forceinline__ uint32_t smem_u32(const void* p) {
    uint32_t a;
    asm("{ .reg .u64 t; cvta.to.shared.u64 t, %1; cvt.u32.u64 %0, t; }" : "=r"(a) : "l"(p));
    return a;
}
#define SWZ(off) ((off) ^ (((off) >> 3) & 0x70))

__device__ __forceinline__ void cp_async16(uint32_t saddr, const void* gptr) {
    asm volatile("cp.async.cg.shared.global [%0], [%1], 16;\n" :: "r"(saddr), "l"(gptr));
}
__device__ __forceinline__ void cp_commit() {
    asm volatile("cp.async.commit_group;\n" ::: "memory");
}
template <int N>
__device__ __forceinline__ void cp_wait() {
    asm volatile("cp.async.wait_group %0;\n" :: "n"(N) : "memory");
}
__device__ __forceinline__ void ldsm_x4(uint32_t& r0, uint32_t& r1, uint32_t& r2,
                                        uint32_t& r3, uint32_t addr) {
    asm volatile("ldmatrix.sync.aligned.m8n8.x4.shared.b16 {%0,%1,%2,%3}, [%4];"
                 : "=r"(r0), "=r"(r1), "=r"(r2), "=r"(r3) : "r"(addr));
}
__device__ __forceinline__ void mma16816(float* c, const uint32_t* a, const uint32_t* b) {
    asm volatile(
        "mma.sync.aligned.m16n8k16.row.col.f32.f16.f16.f32 "
        "{%0,%1,%2,%3}, {%4,%5,%6,%7}, {%8,%9}, {%0,%1,%2,%3};"
        : "+f"(c[0]), "+f"(c[1]), "+f"(c[2]), "+f"(c[3])
        : "r"(a[0]), "r"(a[1]), "r"(a[2]), "r"(a[3]), "r"(b[0]), "r"(b[1]));
}

// ---------------- gate kernel: Wg cached in smem, 16 tokens/block; also emits x16 ----
#define GTOK 16
__global__ void gate_kernel(const float* __restrict__ x, const float* __restrict__ Wg,
                            const float* __restrict__ bg, float* __restrict__ gw,
                            __half* __restrict__ x16) {
    __shared__ float wgs[NE * DD];
    __shared__ float slog[NE];
    int tid = threadIdx.x, wid = tid >> 5, lid = tid & 31;
    for (int i = tid; i < NE * DD / 4; i += 256)
        reinterpret_cast<float4*>(wgs)[i] = reinterpret_cast<const float4*>(Wg)[i];
    // fused x -> fp16 conversion for this block's 16 tokens (x rows are L2-hot here)
    {
        size_t base4 = (size_t)blockIdx.x * GTOK * DD / 4;
        for (int i = tid; i < GTOK * DD / 4; i += 256) {
            float4 v = reinterpret_cast<const float4*>(x)[base4 + i];
            __half h[4] = {__float2half_rn(v.x), __float2half_rn(v.y),
                           __float2half_rn(v.z), __float2half_rn(v.w)};
            *reinterpret_cast<uint2*>(x16 + (base4 + i) * 4) = *reinterpret_cast<uint2*>(h);
        }
    }
    __syncthreads();
    for (int t = 0; t < GTOK; t++) {
        int b = blockIdx.x * GTOK + t;
        const float* xr = x + (size_t)b * DD;
        const float* wr = wgs + wid * DD;
        float s = 0.f;
        for (int i = lid; i < DD; i += 32) s += xr[i] * wr[i];
#pragma unroll
        for (int o = 16; o > 0; o >>= 1) s += __shfl_xor_sync(0xffffffffu, s, o);
        if (lid == 0) slog[wid] = s + bg[wid];
        __syncthreads();
        if (tid == 0) {
            const float invT = 0.36787944117144233f;
            float l[NE], mx = -1e30f;
#pragma unroll
            for (int i = 0; i < NE; i++) { l[i] = slog[i] * invT; mx = fmaxf(mx, l[i]); }
            float p[NE], se = 0.f;
#pragma unroll
            for (int i = 0; i < NE; i++) { p[i] = expf(l[i] - mx); se += p[i]; }
            float inv_se = 1.f / se;
#pragma unroll
            for (int i = 0; i < NE; i++) p[i] *= inv_se;
            bool sel[NE];
#pragma unroll
            for (int i = 0; i < NE; i++) sel[i] = false;
            float ss = 0.f;
            for (int it = 0; it < NAE; it++) {
                int bi = 0; float bv = -1.f;
#pragma unroll
                for (int i = 0; i < NE; i++)
                    if (!sel[i] && p[i] > bv) { bv = p[i]; bi = i; }
                sel[bi] = true; ss += bv;
            }
            float inv = 1.f / (ss + 1e-8f);
#pragma unroll
            for (int i = 0; i < NE; i++)
                gw[(size_t)b * NE + i] = sel[i] ? p[i] * inv : 0.f;
        }
        __syncthreads();
    }
}

// ---------------- per-expert token list (deterministic, token order) ----------------
__global__ void build_lists(const float* __restrict__ gw, int* __restrict__ list,
                            int* __restrict__ cnt) {
    int z = blockIdx.x, tid = threadIdx.x;
    __shared__ int sbase;
    __shared__ int wtot[8];
    if (tid == 0) sbase = 0;
    __syncthreads();
    for (int t0 = 0; t0 < BB; t0 += 256) {
        int b = t0 + tid;
        int act = gw[(size_t)b * NE + z] > 0.f;
        unsigned m = __ballot_sync(0xffffffffu, act);
        int wid = tid >> 5, lid = tid & 31;
        int wpre = __popc(m & ((1u << lid) - 1u));
        if (lid == 31) wtot[wid] = __popc(m);
        __syncthreads();
        int woff = 0;
        for (int w = 0; w < wid; w++) woff += wtot[w];
        if (act) list[(size_t)z * BB + sbase + woff + wpre] = b;
        __syncthreads();
        if (tid == 0) {
            int tot = 0;
            for (int w = 0; w < 8; w++) tot += wtot[w];
            sbase += tot;
        }
        __syncthreads();
    }
    int c = sbase;
    if (tid == 0) cnt[z] = c;
    int cpad = (c + 127) & ~127;
    for (int i = c + tid; i < cpad; i += 256) list[(size_t)z * BB + i] = 0;
}

// ---------------- merged fp32 -> fp16 conversion (W1, W2) ----------------
__global__ void tohalf2_kernel(const float* __restrict__ b, __half* __restrict__ ob, size_t nb4,
                               const float* __restrict__ c, __half* __restrict__ oc, size_t nc4) {
    size_t total = nb4 + nc4;
    size_t i = (size_t)blockIdx.x * blockDim.x + threadIdx.x;
    size_t str = (size_t)gridDim.x * blockDim.x;
    for (; i < total; i += str) {
        const float* src; __half* dst; size_t j;
        if (i < nb4) { src = b; dst = ob; j = i; }
        else { src = c; dst = oc; j = i - nb4; }
        float4 v = reinterpret_cast<const float4*>(src)[j];
        __half h[4] = {__float2half_rn(v.x), __float2half_rn(v.y),
                       __float2half_rn(v.z), __float2half_rn(v.w)};
        *reinterpret_cast<uint2*>(dst + j * 4) = *reinterpret_cast<uint2*>(h);
    }
}

// ---------------- GEMM config: 128x128 tile, BK=64, 2-stage, 2 CTAs/SM ------------
#define TPB 256
#define ST_SZ 32768            // A 16K + B 16K
#define B_OFF 16384
#define ILIST_OFF (2 * ST_SZ)  // 65536
#define SMEM_SZ (2 * ST_SZ + 512)

// compute one BK=64 chunk: acc += A x B (warp tile 64x32)
__device__ __forceinline__ void compute_chunk(uint32_t sbase, int s, int warp_m,
                                              int warp_n, int lid, float acc[4][4][4]) {
    uint32_t aB = sbase + s * ST_SZ;
    uint32_t bB = aB + B_OFF;
    int rA = warp_m * 64 + (lid & 15);
    int rB = warp_n * 32 + (lid & 15);
    int kh = (lid >> 4) * 16;
#pragma unroll
    for (int ks = 0; ks < 4; ks++) {
        int colb = ks * 32 + kh;
        uint32_t a[4][4];
#pragma unroll
        for (int mf = 0; mf < 4; mf++)
            ldsm_x4(a[mf][0], a[mf][1], a[mf][2], a[mf][3],
                    aB + SWZ((uint32_t)((rA + mf * 16) * 128 + colb)));
        uint32_t b[4][2];
#pragma unroll
        for (int pr = 0; pr < 2; pr++) {
            uint32_t r0, r1, r2, r3;
            ldsm_x4(r0, r1, r2, r3, bB + SWZ((uint32_t)((rB + pr * 16) * 128 + colb)));
            b[pr * 2 + 0][0] = r0; b[pr * 2 + 1][0] = r1;
            b[pr * 2 + 0][1] = r2; b[pr * 2 + 1][1] = r3;
        }
#pragma unroll
        for (int mf = 0; mf < 4; mf++)
#pragma unroll
            for (int nf = 0; nf < 4; nf++)
                mma16816(acc[mf][nf], a[mf], b[nf]);
    }
}

// B loader: 128 rows x 64 cols fp16 from row-major [ldB]
__device__ __forceinline__ void load_B(uint32_t sbase, int s, int tid,
                                       const __half* __restrict__ wrow, int ldB, int kk) {
    uint32_t sb = sbase + s * ST_SZ + B_OFF;
#pragma unroll
    for (int i = 0; i < 4; i++) {
        int u = tid + i * TPB;
        int r = u >> 3, seg = u & 7;
        uint32_t off = SWZ((uint32_t)(r * 128 + seg * 16));
        cp_async16(sb + off, wrow + (size_t)r * ldB + kk + seg * 8);
    }
}

// ===================== layer-1 GEMM (gathered A) =====================
__global__ __launch_bounds__(TPB, 2) void gemm1_kernel(
    const __half* __restrict__ x16,           // [BB][DD]
    const __half* __restrict__ w1h,           // [NE][HH][DD]
    const float* __restrict__ b1,             // [NE][HH]
    const float* __restrict__ gw,             // [BB][NE]
    const int* __restrict__ list, const int* __restrict__ cnt,
    __half* __restrict__ h16) {               // [NE][BB][HH] (compacted rows)
    int z = blockIdx.z;
    int m0 = blockIdx.y * 128;
    int cz = cnt[z];
    if (m0 >= cz) return;
    int n0 = blockIdx.x * 128;

    extern __shared__ __align__(1024) char smem[];
    uint32_t sbase = smem_u32(smem);
    int* silist = reinterpret_cast<int*>(smem + ILIST_OFF);
    int tid = threadIdx.x, lid = tid & 31, wid = tid >> 5;
    int warp_m = wid >> 2, warp_n = wid & 3;

    if (tid < 128) silist[tid] = list[(size_t)z * BB + m0 + tid];
    __syncthreads();

    const __half* wrow = w1h + (size_t)z * HH * DD + (size_t)n0 * DD;
    const int NC = DD / 64;    // 16

    float acc[4][4][4];
#pragma unroll
    for (int a = 0; a < 4; a++)
#pragma unroll
        for (int b = 0; b < 4; b++)
#pragma unroll
            for (int c = 0; c < 4; c++) acc[a][b][c] = 0.f;

    auto issue = [&](int ci) {
        int s = ci & 1, kk = ci * 64;
        uint32_t sa = sbase + s * ST_SZ;
#pragma unroll
        for (int i = 0; i < 4; i++) {
            int u = tid + i * TPB;
            int r = u >> 3, seg = u & 7;
            int tok = silist[r];
            uint32_t off = SWZ((uint32_t)(r * 128 + seg * 16));
            cp_async16(sa + off, x16 + (size_t)tok * DD + kk + seg * 8);
        }
        load_B(sbase, s, tid, wrow, DD, kk);
        cp_commit();
    };

    issue(0);
    for (int ci = 0; ci < NC; ci++) {
        if (ci + 1 < NC) { issue(ci + 1); cp_wait<1>(); } else { cp_wait<0>(); }
        __syncthreads();
        compute_chunk(sbase, ci & 1, warp_m, warp_n, lid, acc);
        __syncthreads();
    }

    // epilogue: bias + relu, gw-scale, round to fp16 -> h16[z][m0+row][col]
    int g = lid >> 2, t4 = lid & 3;
    const float* bias = b1 + (size_t)z * HH;
    __half* hz = h16 + (size_t)z * BB * HH;
#pragma unroll
    for (int mf = 0; mf < 4; mf++) {
#pragma unroll
        for (int h = 0; h < 2; h++) {
            int row_l = warp_m * 64 + mf * 16 + g + h * 8;
            int tok = silist[row_l];
            float wv = gw[(size_t)tok * NE + z];
            size_t rbase = (size_t)(m0 + row_l) * HH;
#pragma unroll
            for (int nf = 0; nf < 4; nf++) {
                int col = n0 + warp_n * 32 + nf * 8 + t4 * 2;
                float2 bz = *reinterpret_cast<const float2*>(bias + col);
                float v0 = fmaxf(acc[mf][nf][h * 2 + 0] + bz.x, 0.f) * wv;
                float v1 = fmaxf(acc[mf][nf][h * 2 + 1] + bz.y, 0.f) * wv;
                __half h0 = __float2half_rn(v0);
                __half h1 = __float2half_rn(v1);
                uint32_t hp = ((uint32_t)__half_as_ushort(h1) << 16) |
                              (uint32_t)__half_as_ushort(h0);
                *reinterpret_cast<uint32_t*>(hz + rbase + col) = hp;
            }
        }
    }
}

// ===================== layer-2 GEMM (compacted A, split-K=2, fp16 partials) ========
__global__ __launch_bounds__(TPB, 2) void gemm2_kernel(
    const __half* __restrict__ h16,           // [NE][BB][HH]
    const __half* __restrict__ w2h,           // [NE][OO][HH]
    const int* __restrict__ list, const int* __restrict__ cnt,
    __half* __restrict__ part) {              // [2][NE][BB][OO] fp16
    int zz = blockIdx.z;
    int z = zz & 7;
    int khalf = zz >> 3;                      // 0 or 1
    int m0 = blockIdx.y * 128;
    int cz = cnt[z];
    if (m0 >= cz) return;
    int n0 = blockIdx.x * 128;

    extern __shared__ __align__(1024) char smem[];
    uint32_t sbase = smem_u32(smem);
    int tid = threadIdx.x, lid = tid & 31, wid = tid >> 5;
    int warp_m = wid >> 2, warp_n = wid & 3;

    const __half* abase = h16 + (size_t)z * BB * HH + (size_t)m0 * HH + khalf * (HH / 2);
    const __half* wrow = w2h + (size_t)z * OO * HH + (size_t)n0 * HH + khalf * (HH / 2);
    const int NC = HH / 128;   // 32 chunks of 64 over half of H

    float acc[4][4][4];
#pragma unroll
    for (int a = 0; a < 4; a++)
#pragma unroll
        for (int b = 0; b < 4; b++)
#pragma unroll
            for (int c = 0; c < 4; c++) acc[a][b][c] = 0.f;

    auto issue = [&](int ci) {
        int s = ci & 1, kk = ci * 64;
        uint32_t sa = sbase + s * ST_SZ;
#pragma unroll
        for (int i = 0; i < 4; i++) {
            int u = tid + i * TPB;
            int r = u >> 3, seg = u & 7;
            uint32_t off = SWZ((uint32_t)(r * 128 + seg * 16));
            cp_async16(sa + off, abase + (size_t)r * HH + kk + seg * 8);
        }
        load_B(sbase, s, tid, wrow, HH, kk);
        cp_commit();
    };

    issue(0);
    for (int ci = 0; ci < NC; ci++) {
        if (ci + 1 < NC) { issue(ci + 1); cp_wait<1>(); } else { cp_wait<0>(); }
        __syncthreads();
        compute_chunk(sbase, ci & 1, warp_m, warp_n, lid, acc);
        __syncthreads();
    }

    // epilogue: scatter fp16 partial rows to part[khalf][z][token], mask padded rows
    int g = lid >> 2, t4 = lid & 3;
    __half* pz = part + ((size_t)khalf * NE + z) * BB * OO;
    const int* lrow = list + (size_t)z * BB + m0;
#pragma unroll
    for (int mf = 0; mf < 4; mf++) {
#pragma unroll
        for (int h = 0; h < 2; h++) {
            int row_l = warp_m * 64 + mf * 16 + g + h * 8;
            if (m0 + row_l < cz) {
                int tok = lrow[row_l];
                size_t rbase = (size_t)tok * OO;
#pragma unroll
                for (int nf = 0; nf < 4; nf++) {
                    int col = n0 + warp_n * 32 + nf * 8 + t4 * 2;
                    __half p0 = __float2half_rn(acc[mf][nf][h * 2 + 0]);
                    __half p1 = __float2half_rn(acc[mf][nf][h * 2 + 1]);
                    uint32_t pp = ((uint32_t)__half_as_ushort(p1) << 16) |
                                  (uint32_t)__half_as_ushort(p0);
                    *reinterpret_cast<uint32_t*>(pz + rbase + col) = pp;
                }
            }
        }
    }
}

// ===================== reduce: out = sum halves/experts + sum_z gw*b2 ==============
__global__ void reduce_kernel(const __half* __restrict__ part, const float* __restrict__ b2,
                              const float* __restrict__ gw, float* __restrict__ out) {
    const size_t n4 = (size_t)BB * OO / 4;
    size_t i = (size_t)blockIdx.x * blockDim.x + threadIdx.x;
    if (i >= n4) return;
    size_t b = i / (OO / 4);
    int o4 = (int)(i - b * (OO / 4));
    float4 acc = make_float4(0.f, 0.f, 0.f, 0.f);
#pragma unroll
    for (int z = 0; z < NE; z++) {
        float wv = gw[b * NE + z];
        float4 bz = reinterpret_cast<const float4*>(b2)[(size_t)z * (OO / 4) + o4];
        acc.x += wv * bz.x; acc.y += wv * bz.y;
        acc.z += wv * bz.z; acc.w += wv * bz.w;
        if (wv > 0.f) {
            size_t ebase = (size_t)z * BB * OO + b * OO + (size_t)o4 * 4;
            const __half2* p0 = reinterpret_cast<const __half2*>(part + ebase);
            const __half2* p1 = reinterpret_cast<const __half2*>(part +
                                  (size_t)NE * BB * OO + ebase);
            float2 a0 = __half22float2(p0[0]);
            float2 a1 = __half22float2(p0[1]);
            float2 c0 = __half22float2(p1[0]);
            float2 c1 = __half22float2(p1[1]);
            acc.x += a0.x + c0.x; acc.y += a0.y + c0.y;
            acc.z += a1.x + c1.x; acc.w += a1.y + c1.y;
        }
    }
    reinterpret_cast<float4*>(out)[i] = acc;
}

// ---------------- host launcher ----------------
extern "C" void kernel_launch(void* const* d_in, const int* in_sizes, int n_in,
                              void* d_out, int out_size) {
    const float* x  = (const float*)d_in[0];
    const float* W1 = (const float*)d_in[1];
    const float* b1 = (const float*)d_in[2];
    const float* W2 = (const float*)d_in[3];
    const float* b2 = (const float*)d_in[4];
    const float* Wg = (const float*)d_in[5];
    const float* bg = (const float*)d_in[6];
    float* out = (float*)d_out;

    void *px16, *pw1h, *pw2h, *ph16, *pgw, *ppart, *plist, *pcnt;
    cudaGetSymbolAddress(&px16, g_x16);
    cudaGetSymbolAddress(&pw1h, g_w1h);
    cudaGetSymbolAddress(&pw2h, g_w2h);
    cudaGetSymbolAddress(&ph16, g_h16);
    cudaGetSymbolAddress(&pgw, g_gw);
    cudaGetSymbolAddress(&ppart, g_part);
    cudaGetSymbolAddress(&plist, g_list);
    cudaGetSymbolAddress(&pcnt, g_cnt);

    cudaFuncSetAttribute(gemm1_kernel, cudaFuncAttributeMaxDynamicSharedMemorySize, SMEM_SZ);
    cudaFuncSetAttribute(gemm2_kernel, cudaFuncAttributeMaxDynamicSharedMemorySize, SMEM_SZ);

    gate_kernel<<<BB / GTOK, 256>>>(x, Wg, bg, (float*)pgw, (__half*)px16);
    build_lists<<<NE, 256>>>((const float*)pgw, (int*)plist, (int*)pcnt);
    tohalf2_kernel<<<16384, 256>>>(
        W1, (__half*)pw1h, (size_t)NE * HH * DD / 4,
        W2, (__half*)pw2h, (size_t)NE * OO * HH / 4);

    // layer 1: compacted tokens per expert
    gemm1_kernel<<<dim3(HH / 128, BB / 128, NE), TPB, SMEM_SZ>>>(
        (const __half*)px16, (const __half*)pw1h, b1, (const float*)pgw,
        (const int*)plist, (const int*)pcnt, (__half*)ph16);

    // layer 2: compacted rows, split-K=2, fp16 partials
    gemm2_kernel<<<dim3(OO / 128, BB / 128, 2 * NE), TPB, SMEM_SZ>>>(
        (const __half*)ph16, (const __half*)pw2h,
        (const int*)plist, (const int*)pcnt, (__half*)ppart);

    reduce_kernel<<<(BB * OO / 4 + 255) / 256, 256>>>(
        (const __half*)ppart, b2, (const float*)pgw, out);
}